// round 16
// baseline (speedup 1.0000x reference)
#include <cuda_runtime.h>
#include <math.h>

#define NE    1024
#define NIN   64
#define HID   128
#define NOUT  64
#define ND    48
#define NBLK  256      // 2 blocks/SM co-resident (regs<=128, smem ~37KB)

// Scratch (__device__ globals per allocation-free rule)
__device__ float g_A [NE * HID];      // A = x@W1a + b1, [i][h]
__device__ float g_B [NE * HID];      // B = x@W1b,      [i][h]
__device__ float g_Bt[HID * NE];      // B transposed,   [h][i]
__device__ float g_Fp[2][ND * HID];   // partner-half partial F sums (no atomics)
__device__ float g_C [ND * HID];      // Chebyshev coeffs [k][h]
__device__ int   g_MaxI[HID];         // per-h max|A| (ordered-int atomicMax; idempotent)
__device__ unsigned g_barcnt = 0;     // barrier arrival counter (returns to 0 each use)
__device__ unsigned g_barph  = 0;     // barrier phase (monotonic across graph replays)

__device__ __forceinline__ float tanh_fast(float x) {
    float y;
    asm("tanh.approx.f32 %0, %1;" : "=f"(y) : "f"(x));
    return y;
}

// Grid-wide barrier: all NBLK blocks co-resident. Monotonic phase (replay-safe).
__device__ __forceinline__ void grid_barrier(unsigned target) {
    __syncthreads();
    if (threadIdx.x == 0) {
        __threadfence();
        const unsigned old = atomicAdd(&g_barcnt, 1);
        if (old == NBLK - 1) {
            g_barcnt = 0;
            __threadfence();
            atomicAdd(&g_barph, 1);
        } else {
            while ((int)(*(volatile unsigned*)&g_barph - target) < 0)
                __nanosleep(32);
        }
        __threadfence();
    }
    __syncthreads();
}

// Overlapping smem for the phases (kept < 48KB static total incl. sW2)
struct SmemProj { float sx[4][NIN]; float s_ab[8][HID]; };            // 5 KB
struct SmemA    { float nodes[ND]; float red[8][ND]; float F[ND]; };  // ~1.9 KB
struct SmemB    { float sacc[4][HID]; };                              // 2 KB
union SmemU { SmemProj proj; SmemA pa; SmemB pb; };

__global__ void __launch_bounds__(256, 2)
k_all(const float* __restrict__ x,  const float* __restrict__ W1,
      const float* __restrict__ b1, const float* __restrict__ W2,
      const float* __restrict__ b2, float* __restrict__ out) {
    const int tid = threadIdx.x;
    const int blk = blockIdx.x;

    __shared__ SmemU u;
    __shared__ float sW2[HID * NOUT];   // 32 KB
    __shared__ unsigned s_ph0;

    if (tid == 0) s_ph0 = *(volatile unsigned*)&g_barph;

    // stage W2 into smem (overlaps phase-1 compute)
    {
        const float4* src = reinterpret_cast<const float4*>(W2);
        float4*       dst = reinterpret_cast<float4*>(sW2);
#pragma unroll
        for (int k = 0; k < 8; k++) dst[k * 256 + tid] = src[k * 256 + tid];
    }

    // ---------------- Phase 1: projection (4 rows per block) ----------------
    {
        const int i0 = blk * 4;
        u.proj.sx[tid >> 6][tid & 63] = x[i0 * NIN + tid];   // 4 rows x 64
        __syncthreads();

        const int fh = tid >> 7;         // f-half
        const int h  = tid & 127;
        const float binit = (fh == 0) ? b1[h] : 0.f;
        float a[4], b[4];
#pragma unroll
        for (int r = 0; r < 4; r++) { a[r] = binit; b[r] = 0.f; }

        const int f0 = fh * 32;
#pragma unroll
        for (int ff = 0; ff < 32; ff++) {
            const int f = f0 + ff;
            const float w1a = W1[f * HID + h];
            const float w1b = W1[(NIN + f) * HID + h];
#pragma unroll
            for (int r = 0; r < 4; r++) {
                a[r] = fmaf(u.proj.sx[r][f], w1a, a[r]);
                b[r] = fmaf(u.proj.sx[r][f], w1b, b[r]);
            }
        }
        if (fh == 1) {
#pragma unroll
            for (int r = 0; r < 4; r++) {
                u.proj.s_ab[r][h]     = a[r];
                u.proj.s_ab[4 + r][h] = b[r];
            }
        }
        __syncthreads();
        if (fh == 0) {
            float m = 0.f;
#pragma unroll
            for (int r = 0; r < 4; r++) {
                const float av = a[r] + u.proj.s_ab[r][h];
                const float bv = b[r] + u.proj.s_ab[4 + r][h];
                const int i = i0 + r;
                g_A[i * HID + h] = av;
                g_B[i * HID + h] = bv;
                g_Bt[h * NE + i] = bv;
                m = fmaxf(m, fabsf(av));
            }
            atomicMax(&g_MaxI[h], __float_as_int(m));  // m>=0: int order == float order
        }
    }

    const unsigned ph0 = s_ph0;
    grid_barrier(ph0 + 1);   // all A/B/Bt/MaxI visible

    // ---- Phase 2: partial F_h sums; block = (h, partner-half), balanced ----
    {
        const int h    = blk >> 1;
        const int half = blk & 1;
        const float r = fmaxf(__int_as_float(g_MaxI[h]), 1e-4f);
        if (tid < ND)
            u.pa.nodes[tid] = r * cospif((tid + 0.5f) * (1.0f / ND));
        __syncthreads();

        float part[ND];
#pragma unroll
        for (int j = 0; j < ND; j++) part[j] = 0.f;

        const float* __restrict__ rowB = g_Bt + h * NE + half * 512;
#pragma unroll
        for (int m = 0; m < 2; m++) {
            const float bv = rowB[m * 256 + tid];
#pragma unroll
            for (int j = 0; j < ND; j++)
                part[j] += tanh_fast(u.pa.nodes[j] + bv);
        }

        const int w = tid >> 5, lane = tid & 31;
#pragma unroll
        for (int j = 0; j < ND; j++) {
            float v = part[j];
#pragma unroll
            for (int d = 16; d; d >>= 1)
                v += __shfl_xor_sync(0xffffffffu, v, d);
            if (lane == 0) u.pa.red[w][j] = v;
        }
        __syncthreads();
        if (tid < ND) {
            float F = 0.f;
#pragma unroll
            for (int w8 = 0; w8 < 8; w8++) F += u.pa.red[w8][tid];
            g_Fp[half][tid * HID + h] = F;   // disjoint slot: deterministic
        }
    }

    grid_barrier(ph0 + 2);   // all partial F visible

    // ---------- Phase 2b: DCT (blocks 0..127 only; h = blk) ----------
    if (blk < HID) {
        const int h = blk;
        if (tid < ND)
            u.pa.F[tid] = g_Fp[0][tid * HID + h] + g_Fp[1][tid * HID + h];
        __syncthreads();
        if (tid < ND) {
            const int k = tid;
            float s = 0.f;
#pragma unroll 8
            for (int j = 0; j < ND; j++)
                s = fmaf(u.pa.F[j], cospif((float)k * (j + 0.5f) * (1.0f / ND)), s);
            g_C[k * HID + h] = s * ((k == 0) ? (1.0f / ND) : (2.0f / ND));
        }
    }

    grid_barrier(ph0 + 3);   // all coefficients visible

    // ------ Phase 3: Clenshaw + self-term + mean + W2 epilogue (4 rows) ------
    {
        const int hg = tid >> 7;          // half-block: 2 rows each
        const int h  = tid & 127;
        const int ra = blk * 4 + hg * 2;

        float creg[ND];                   // batched preload (MLP~48)
#pragma unroll
        for (int k = 0; k < ND; k++) creg[k] = g_C[k * HID + h];

        const float rinv = 1.0f / fmaxf(__int_as_float(g_MaxI[h]), 1e-4f);

        const float A0 = g_A[(ra + 0) * HID + h];
        const float A1 = g_A[(ra + 1) * HID + h];
        const float B0 = g_B[(ra + 0) * HID + h];
        const float B1 = g_B[(ra + 1) * HID + h];
        const float t0 = A0 * rinv, t1 = A1 * rinv;
        const float t0x2 = t0 + t0, t1x2 = t1 + t1;

        float p1_0 = 0.f, p2_0 = 0.f, p1_1 = 0.f, p2_1 = 0.f;
#pragma unroll
        for (int k = ND - 1; k >= 1; k--) {
            const float ak = creg[k];
            const float n0 = fmaf(t0x2, p1_0, ak - p2_0);
            const float n1 = fmaf(t1x2, p1_1, ak - p2_1);
            p2_0 = p1_0; p1_0 = n0;
            p2_1 = p1_1; p1_1 = n1;
        }
        const float inv = 1.0f / (float)(NE - 1);
        {
            float F0 = fmaf(t0, p1_0, creg[0] - p2_0) - tanh_fast(A0 + B0);
            float F1 = fmaf(t1, p1_1, creg[0] - p2_1) - tanh_fast(A1 + B1);
            u.pb.sacc[hg * 2 + 0][h] = F0 * inv;
            u.pb.sacc[hg * 2 + 1][h] = F1 * inv;
        }
        __syncthreads();

        // 4 rows x 64 outs = 256 outputs, 1 per thread, 4-split accumulators
        const int rr = tid >> 6;
        const int o  = tid & (NOUT - 1);
        float a0 = 0.f, a1 = 0.f, a2 = 0.f, a3 = 0.f;
#pragma unroll
        for (int hh = 0; hh < 32; hh++) {
            a0 = fmaf(u.pb.sacc[rr][hh],      sW2[hh * NOUT + o],        a0);
            a1 = fmaf(u.pb.sacc[rr][32 + hh], sW2[(32 + hh) * NOUT + o], a1);
            a2 = fmaf(u.pb.sacc[rr][64 + hh], sW2[(64 + hh) * NOUT + o], a2);
            a3 = fmaf(u.pb.sacc[rr][96 + hh], sW2[(96 + hh) * NOUT + o], a3);
        }
        out[(blk * 4 + rr) * NOUT + o] = b2[o] + ((a0 + a1) + (a2 + a3));
    }
}

// ---------------------------------------------------------------------------
extern "C" void kernel_launch(void* const* d_in, const int* in_sizes, int n_in,
                              void* d_out, int out_size) {
    const float* x  = (const float*)d_in[0];
    const float* W1 = (const float*)d_in[1];
    const float* b1 = (const float*)d_in[2];
    const float* W2 = (const float*)d_in[3];
    const float* b2 = (const float*)d_in[4];
    float* out = (float*)d_out;

    k_all<<<NBLK, 256>>>(x, W1, b1, W2, b2, out);
}

// round 17
// speedup vs baseline: 1.1094x; 1.1094x over previous
#include <cuda_runtime.h>
#include <math.h>

#define NE    1024
#define NIN   64
#define HID   128
#define NOUT  64
#define ND    48
#define NBLK  128      // one block per SM; co-residency guaranteed (128 < 148)
#define NTHR  512      // 16 warps/SM = 4 per SMSP

// Scratch (__device__ globals per allocation-free rule)
__device__ float g_A [NE * HID];    // A = x@W1a + b1, [i][h]
__device__ float g_B [NE * HID];    // B = x@W1b,      [i][h]
__device__ float g_Bt[HID * NE];    // B transposed,   [h][i]
__device__ float g_C [ND * HID];    // Chebyshev coeffs [k][h]
__device__ int   g_MaxI[HID];       // per-h max|A| (ordered-int atomicMax; idempotent)
__device__ unsigned g_barcnt = 0;   // barrier arrival counter (returns to 0 each use)
__device__ unsigned g_barph  = 0;   // barrier phase (monotonic across graph replays)

__device__ __forceinline__ float tanh_fast(float x) {
    float y;
    asm("tanh.approx.f32 %0, %1;" : "=f"(y) : "f"(x));
    return y;
}

// Grid-wide barrier: all NBLK blocks co-resident. Monotonic phase (replay-safe).
__device__ __forceinline__ void grid_barrier(unsigned target) {
    __syncthreads();
    if (threadIdx.x == 0) {
        __threadfence();
        const unsigned old = atomicAdd(&g_barcnt, 1);
        if (old == NBLK - 1) {
            g_barcnt = 0;
            __threadfence();
            atomicAdd(&g_barph, 1);
        } else {
            while ((int)(*(volatile unsigned*)&g_barph - target) < 0)
                __nanosleep(32);
        }
        __threadfence();
    }
    __syncthreads();
}

// Overlapping smem for the phases (static total must stay < 48 KB with sW2)
struct SmemProj { float sx[8][NIN]; float s_a[8][HID]; float s_b[8][HID]; }; // 10 KB
struct SmemA    { float nodes[ND]; float red[16][ND]; float F[ND]; };        // ~3.5 KB
struct SmemB    { float sacc[8][HID]; };                                     // 4 KB
union SmemU { SmemProj proj; SmemA pa; SmemB pb; };

__global__ void __launch_bounds__(NTHR, 1)
k_all(const float* __restrict__ x,  const float* __restrict__ W1,
      const float* __restrict__ b1, const float* __restrict__ W2,
      const float* __restrict__ b2, float* __restrict__ out) {
    const int tid = threadIdx.x;
    const int blk = blockIdx.x;

    __shared__ SmemU u;
    __shared__ float sW2[HID * NOUT];   // 32 KB
    __shared__ unsigned s_ph0;

    if (tid == 0) s_ph0 = *(volatile unsigned*)&g_barph;

    // stage W2 into smem (overlaps phase-1 compute; done once per block)
    {
        const float4* src = reinterpret_cast<const float4*>(W2);
        float4*       dst = reinterpret_cast<float4*>(sW2);
#pragma unroll
        for (int k = 0; k < 4; k++) dst[k * NTHR + tid] = src[k * NTHR + tid];
    }

    // ------------- Phase 1: projection (8 rows per block) -------------
    // tid = (fh, rg, h): fh = f-half, rg = row-quad, h = hidden unit.
    {
        const int i0 = blk * 8;
        if (tid < 512) u.proj.sx[tid >> 6][tid & 63] = x[i0 * NIN + tid];
        __syncthreads();

        const int h  = tid & 127;
        const int rg = (tid >> 7) & 1;   // row quad: rows rg*4 .. rg*4+3
        const int fh = tid >> 8;         // f half
        const int rbase = rg * 4;

        const float binit = (fh == 0) ? b1[h] : 0.f;
        float a[4], b[4];
#pragma unroll
        for (int r = 0; r < 4; r++) { a[r] = binit; b[r] = 0.f; }

        const int f0 = fh * 32;
#pragma unroll
        for (int ff = 0; ff < 32; ff++) {
            const int f = f0 + ff;
            const float w1a = W1[f * HID + h];
            const float w1b = W1[(NIN + f) * HID + h];
#pragma unroll
            for (int r = 0; r < 4; r++) {
                a[r] = fmaf(u.proj.sx[rbase + r][f], w1a, a[r]);
                b[r] = fmaf(u.proj.sx[rbase + r][f], w1b, b[r]);
            }
        }
        if (fh == 1) {
#pragma unroll
            for (int r = 0; r < 4; r++) {
                u.proj.s_a[rbase + r][h] = a[r];
                u.proj.s_b[rbase + r][h] = b[r];
            }
        }
        __syncthreads();
        if (fh == 0) {
            float m = 0.f;
#pragma unroll
            for (int r = 0; r < 4; r++) {
                const float av = a[r] + u.proj.s_a[rbase + r][h];
                const float bv = b[r] + u.proj.s_b[rbase + r][h];
                const int i = i0 + rbase + r;
                g_A[i * HID + h] = av;
                g_B[i * HID + h] = bv;
                g_Bt[h * NE + i] = bv;
                m = fmaxf(m, fabsf(av));
            }
            atomicMax(&g_MaxI[h], __float_as_int(m));  // m>=0: int order == float order
        }
    }

    const unsigned ph0 = s_ph0;
    grid_barrier(ph0 + 1);   // all A/B/Bt/MaxI visible

    // ---- Phase 2: F_h at ND nodes + DCT, one block per h (block-local) ----
    {
        const int h = blk;
        const float r = fmaxf(__int_as_float(g_MaxI[h]), 1e-4f);
        if (tid < ND)
            u.pa.nodes[tid] = r * cospif((tid + 0.5f) * (1.0f / ND));
        __syncthreads();

        float part[ND];
#pragma unroll
        for (int j = 0; j < ND; j++) part[j] = 0.f;

        const float* __restrict__ rowB = g_Bt + h * NE;
#pragma unroll
        for (int m = 0; m < 2; m++) {
            const float bv = rowB[m * NTHR + tid];
#pragma unroll
            for (int j = 0; j < ND; j++)
                part[j] += tanh_fast(u.pa.nodes[j] + bv);
        }

        const int w = tid >> 5, lane = tid & 31;
#pragma unroll
        for (int j = 0; j < ND; j++) {
            float v = part[j];
#pragma unroll
            for (int d = 16; d; d >>= 1)
                v += __shfl_xor_sync(0xffffffffu, v, d);
            if (lane == 0) u.pa.red[w][j] = v;
        }
        __syncthreads();
        if (tid < ND) {
            float F = 0.f;
#pragma unroll
            for (int w16 = 0; w16 < 16; w16++) F += u.pa.red[w16][tid];
            u.pa.F[tid] = F;
        }
        __syncthreads();
        if (tid < ND) {
            const int k = tid;
            float s = 0.f;
#pragma unroll 8
            for (int j = 0; j < ND; j++)
                s = fmaf(u.pa.F[j], cospif((float)k * (j + 0.5f) * (1.0f / ND)), s);
            g_C[k * HID + h] = s * ((k == 0) ? (1.0f / ND) : (2.0f / ND));
        }
    }

    grid_barrier(ph0 + 2);   // all coefficients visible

    // ---- Phase 3: Clenshaw + self-term + mean + W2 epilogue (8 rows) ----
    {
        const int h  = tid & 127;
        const int qg = tid >> 7;            // 0..3, each owns 2 rows
        const int ra = blk * 8 + qg * 2;

        float creg[ND];                     // batched preload (MLP~48)
#pragma unroll
        for (int k = 0; k < ND; k++) creg[k] = g_C[k * HID + h];

        const float rinv = 1.0f / fmaxf(__int_as_float(g_MaxI[h]), 1e-4f);

        const float A0 = g_A[(ra + 0) * HID + h];
        const float A1 = g_A[(ra + 1) * HID + h];
        const float B0 = g_B[(ra + 0) * HID + h];
        const float B1 = g_B[(ra + 1) * HID + h];
        const float t0 = A0 * rinv, t1 = A1 * rinv;
        const float t0x2 = t0 + t0, t1x2 = t1 + t1;

        float p1_0 = 0.f, p2_0 = 0.f, p1_1 = 0.f, p2_1 = 0.f;
#pragma unroll
        for (int k = ND - 1; k >= 1; k--) {
            const float ak = creg[k];
            const float n0 = fmaf(t0x2, p1_0, ak - p2_0);
            const float n1 = fmaf(t1x2, p1_1, ak - p2_1);
            p2_0 = p1_0; p1_0 = n0;
            p2_1 = p1_1; p1_1 = n1;
        }
        const float inv = 1.0f / (float)(NE - 1);
        {
            float F0 = fmaf(t0, p1_0, creg[0] - p2_0) - tanh_fast(A0 + B0); // excl p==i
            float F1 = fmaf(t1, p1_1, creg[0] - p2_1) - tanh_fast(A1 + B1);
            u.pb.sacc[qg * 2 + 0][h] = F0 * inv;
            u.pb.sacc[qg * 2 + 1][h] = F1 * inv;
        }
        __syncthreads();

        // 8 rows x 64 outs = 512 outputs, exactly 1 per thread.
        const int rr = tid >> 6;            // 0..7 (warp-uniform: broadcast sacc)
        const int o  = tid & (NOUT - 1);    // lane-linear: coalesced sW2
        float a0 = 0.f, a1 = 0.f, a2 = 0.f, a3 = 0.f;
#pragma unroll
        for (int hh = 0; hh < 32; hh++) {
            a0 = fmaf(u.pb.sacc[rr][hh],      sW2[hh * NOUT + o],        a0);
            a1 = fmaf(u.pb.sacc[rr][32 + hh], sW2[(32 + hh) * NOUT + o], a1);
            a2 = fmaf(u.pb.sacc[rr][64 + hh], sW2[(64 + hh) * NOUT + o], a2);
            a3 = fmaf(u.pb.sacc[rr][96 + hh], sW2[(96 + hh) * NOUT + o], a3);
        }
        out[(blk * 8 + rr) * NOUT + o] = b2[o] + ((a0 + a1) + (a2 + a3));
    }
}

// ---------------------------------------------------------------------------
extern "C" void kernel_launch(void* const* d_in, const int* in_sizes, int n_in,
                              void* d_out, int out_size) {
    const float* x  = (const float*)d_in[0];
    const float* W1 = (const float*)d_in[1];
    const float* b1 = (const float*)d_in[2];
    const float* W2 = (const float*)d_in[3];
    const float* b2 = (const float*)d_in[4];
    float* out = (float*)d_out;

    k_all<<<NBLK, NTHR>>>(x, W1, b1, W2, b2, out);
}